// round 7
// baseline (speedup 1.0000x reference)
#include <cuda_runtime.h>
#include <cuda_bf16.h>

// DinoPool == masked average pooling of x over 512-row blocks.
// x: [B=4, S=4096, C=384] fp32 -> out same shape.
// out[b, s, c] = mean_{r in block(s)} x[b, r, c].
//
// R7: R6 structure (384 CTAs x 256 thr, full 148-SM coverage) with the
// __ldcs regression removed: x loads use the default/read-only path so x
// stays L2-resident across graph replays (working set 50MB << 126MB L2).
// Steady state should then be DRAM-free; read phase runs at L2-hit speed
// and the kernel sits on the ~3.1TB/s write-path floor.

static constexpr int S       = 4096;
static constexpr int C       = 384;
static constexpr int C4      = C / 4;      // 96 float4 per row
static constexpr int BLOCK   = 512;
static constexpr int NBLK    = 8;
static constexpr int NBAT    = 4;
static constexpr int CH4     = 8;          // float4 columns per CTA (128B)
static constexpr int NCH     = C4 / CH4;   // 12 chunks
static constexpr int NT      = 256;
static constexpr int RG      = NT / CH4;   // 32 rowgroups
static constexpr int RPT     = BLOCK / RG; // 16 rows per thread

__global__ __launch_bounds__(NT, 8)
void dinopool_kernel(const float* __restrict__ x, float* __restrict__ out) {
    const int chunk = blockIdx.x;   // 0..11
    const int blk   = blockIdx.y;   // 0..7
    const int bat   = blockIdx.z;   // 0..3

    const int col = threadIdx.x & (CH4 - 1);   // 0..7
    const int rg  = threadIdx.x >> 3;          // 0..31

    const float4* __restrict__ x4 = reinterpret_cast<const float4*>(x);
    float4* __restrict__ o4       = reinterpret_cast<float4*>(out);

    // float4 index of (row rg*RPT, this column) within this (bat, blk)
    const size_t base = ((size_t)bat * S + (size_t)blk * BLOCK
                         + (size_t)rg * RPT) * C4
                        + (size_t)chunk * CH4 + col;

    // ---- accumulate 16 rows per thread (L2-persistent loads) ----
    float4 acc = make_float4(0.f, 0.f, 0.f, 0.f);
    #pragma unroll
    for (int r = 0; r < RPT; r++) {
        float4 v = __ldg(&x4[base + (size_t)r * C4]);
        acc.x += v.x; acc.y += v.y; acc.z += v.z; acc.w += v.w;
    }

    // ---- tree reduction across 32 rowgroups in smem ----
    __shared__ float4 sm[RG][CH4];
    sm[rg][col] = acc;
    __syncthreads();
    #pragma unroll
    for (int s = RG / 2; s >= 1; s >>= 1) {
        if (rg < s) {
            float4 a = sm[rg][col];
            float4 b = sm[rg + s][col];
            a.x += b.x; a.y += b.y; a.z += b.z; a.w += b.w;
            sm[rg][col] = a;
        }
        __syncthreads();
    }

    // ---- broadcast mean to this CTA's 512 output rows ----
    float4 mean = sm[0][col];
    const float inv = 1.0f / (float)BLOCK;
    mean.x *= inv; mean.y *= inv; mean.z *= inv; mean.w *= inv;

    #pragma unroll
    for (int r = 0; r < RPT; r++) {
        o4[base + (size_t)r * C4] = mean;
    }
}

extern "C" void kernel_launch(void* const* d_in, const int* in_sizes, int n_in,
                              void* d_out, int out_size) {
    const float* x = (const float*)d_in[0];   // [4, 4096, 384] fp32
    float* out     = (float*)d_out;
    (void)in_sizes; (void)n_in; (void)out_size;

    dim3 grid(NCH /*12*/, NBLK /*8*/, NBAT /*4*/);   // 384 CTAs
    dinopool_kernel<<<grid, NT>>>(x, out);
}